// round 15
// baseline (speedup 1.0000x reference)
#include <cuda_runtime.h>
#include <cuda_fp16.h>
#include <cstdint>

// Problem constants
#define B_   8
#define C_   128
#define H_   64
#define W_   64
#define COUT 128
#define KO   18
#define CK   1152          // C_*9, K reordered as k9*128 + c
#define KC   64            // K per chunk
#define NCHUNK (CK / KC)   // 18
#define MOFF 32            // KO padded to 32 for MMA

__device__ __forceinline__ uint32_t smem_to_u32(const void* p) {
    uint32_t a;
    asm("{ .reg .u64 t; cvta.to.shared.u64 t, %1; cvt.u32.u64 %0, t; }" : "=r"(a) : "l"(p));
    return a;
}

// ldmatrix x4 (non-transposed)
#define LDSM4(r0, r1, r2, r3, addr) \
    asm volatile("ldmatrix.sync.aligned.m8n8.x4.shared.b16 {%0,%1,%2,%3}, [%4];" \
                 : "=r"(r0), "=r"(r1), "=r"(r2), "=r"(r3) : "r"(addr))

// fp16 mma with fp32 accumulate
#define MMA16816(c, a0, a1, a2, a3, b0, b1) \
    asm volatile("mma.sync.aligned.m16n8k16.row.col.f32.f16.f16.f32 " \
                 "{%0,%1,%2,%3},{%4,%5,%6,%7},{%8,%9},{%0,%1,%2,%3};" \
                 : "+f"((c)[0]), "+f"((c)[1]), "+f"((c)[2]), "+f"((c)[3]) \
                 : "r"(a0), "r"(a1), "r"(a2), "r"(a3), "r"(b0), "r"(b1))

// swizzled tile offset for k_offmma (128B rows, XOR on 16B granule)
__device__ __forceinline__ uint32_t sw_off(int row, int g16) {
    return (uint32_t)(row * 128 + ((g16 ^ (row & 7)) << 4));
}

// ---------------- device scratch ----------------
__device__ float g_off[B_ * KO * H_ * W_];
__device__ __align__(16) __half g_wh[COUT * CK];            // deform weights fp16, K = k9*128 + c
__device__ __align__(16) __half g_woh[MOFF * CK];           // offset-conv weights fp16, M padded
__device__ __align__(16) uint2  g_xq[B_ * C_ * H_ * W_];    // 2x2 fp16 quads per (c,h,w)

// ---------------- kernel 0a: fp16 deform weights, k9-major reorder ----------------
__global__ void k_prep_w(const float* __restrict__ w_def) {
    int i = blockIdx.x * blockDim.x + threadIdx.x;
    if (i < COUT * CK) {
        int cout = i / CK;
        int rem  = i - cout * CK;
        int k9   = rem >> 7;
        int c    = rem & 127;
        g_wh[i] = __float2half(w_def[(cout * C_ + c) * 9 + k9]);
    }
}

// ---------------- kernel 0b: fp16 offset weights, k9-major, M padded to 32 ----------------
__global__ void k_prep_woff(const float* __restrict__ w_off) {
    int i = blockIdx.x * blockDim.x + threadIdx.x;
    if (i < MOFF * CK) {
        int m   = i / CK;
        int rem = i - m * CK;
        int k9  = rem >> 7;
        int c   = rem & 127;
        float v = (m < KO) ? w_off[(m * C_ + c) * 9 + k9] : 0.f;
        g_woh[i] = __float2half(v);
    }
}

// ---------------- kernel 0c: 2x2 quad-pack x (fp16, row/col clamped) ----------------
// grid = B_*C_, block 256. Each thread handles 16 quads.
__global__ void k_prep_xq(const float* __restrict__ x) {
    int bc_ = blockIdx.x;                 // b*C_ + c
    const float* xp = x + (size_t)bc_ * (H_ * W_);
    uint2* dst = g_xq + (size_t)bc_ * (H_ * W_);
    for (int i = threadIdx.x; i < H_ * W_; i += 256) {
        int h = i >> 6, w = i & 63;
        int h1 = min(h + 1, H_ - 1), w1 = min(w + 1, W_ - 1);
        float a00 = xp[h * W_ + w],   a01 = xp[h * W_ + w1];
        float a10 = xp[h1 * W_ + w],  a11 = xp[h1 * W_ + w1];
        __half2 lo = __floats2half2_rn(a00, a01);
        __half2 hi = __floats2half2_rn(a10, a11);
        uint2 q;
        q.x = *(uint32_t*)&lo;
        q.y = *(uint32_t*)&hi;
        dst[i] = q;
    }
}

// ---------------- kernel 1: offsets conv via fp16 mma.sync (R13 version, kept) ----------------
__global__ void __launch_bounds__(256)
k_offmma(const float* __restrict__ x, const float* __restrict__ b_off) {
    __shared__ __align__(16) char smA[MOFF * 128];   // 4096
    __shared__ __align__(16) char smB[64 * 128];     // 8192
    uint32_t sbA = smem_to_u32(smA);
    uint32_t sbB = smem_to_u32(smB);

    int b   = blockIdx.x >> 6;
    int ho  = blockIdx.x & 63;
    int tid = threadIdx.x;
    int wid = tid >> 5;
    int lane = tid & 31;

    const int wm = wid & 1;
    const int wn = wid >> 1;

    float c[2][4];
    #pragma unroll
    for (int i = 0; i < 2; i++)
        #pragma unroll
        for (int j = 0; j < 4; j++) c[i][j] = 0.f;

    const int n  = tid & 63;
    const int t4 = tid >> 6;

    const int g8 = lane >> 3;
    const int lr = lane & 7;
    const int a_row = wm * 16 + lr + (g8 & 1) * 8;
    const int b_row = wn * 16 + lr + (g8 >> 1) * 8;
    const int ar7 = a_row & 7;
    const int br7 = b_row & 7;
    const int agl = g8 >> 1;
    const int bgl = g8 & 1;

    const int a_m  = tid >> 3;
    const int a_g  = tid & 7;

    for (int chunk = 0; chunk < NCHUNK; chunk++) {
        const int k9 = chunk >> 1;
        const int c0 = (chunk & 1) * 64;
        const int ky = k9 / 3;
        const int kx = k9 - ky * 3;

        __syncthreads();

        {
            const char* src = (const char*)g_woh + (size_t)a_m * (CK * 2)
                              + chunk * (KC * 2) + a_g * 16;
            *(uint4*)(smA + sw_off(a_m, a_g)) = *(const uint4*)src;
        }

        {
            int row = ho + ky - 1;
            int col = n + kx - 1;
            bool ok = ((unsigned)row < (unsigned)H_) && ((unsigned)col < (unsigned)W_);
            const float* base = x + (((size_t)(b * C_ + c0 + t4 * 16) * H_ + row) * W_ + col);
            uint32_t o[8];
            #pragma unroll
            for (int q = 0; q < 8; q++) {
                float va = ok ? __ldg(base + (size_t)(2 * q)     * (H_ * W_)) : 0.f;
                float vb = ok ? __ldg(base + (size_t)(2 * q + 1) * (H_ * W_)) : 0.f;
                __half2 h2 = __floats2half2_rn(va, vb);
                o[q] = *(uint32_t*)&h2;
            }
            *(uint4*)(smB + sw_off(n, 2 * t4))     = make_uint4(o[0], o[1], o[2], o[3]);
            *(uint4*)(smB + sw_off(n, 2 * t4 + 1)) = make_uint4(o[4], o[5], o[6], o[7]);
        }
        __syncthreads();

        #pragma unroll
        for (int ks = 0; ks < 4; ks++) {
            uint32_t a0, a1, a2, a3;
            LDSM4(a0, a1, a2, a3, sbA + (uint32_t)(a_row * 128) + ((uint32_t)((2 * ks + agl) ^ ar7) << 4));
            uint32_t b0, b1, b2, b3;
            LDSM4(b0, b1, b2, b3, sbB + (uint32_t)(b_row * 128) + ((uint32_t)((2 * ks + bgl) ^ br7) << 4));
            MMA16816(c[0], a0, a1, a2, a3, b0, b1);
            MMA16816(c[1], a0, a1, a2, a3, b2, b3);
        }
    }

    {
        int ko0 = wm * 16 + (lane >> 2);
        int ko1 = ko0 + 8;
        float bias0 = (ko0 < KO) ? __ldg(b_off + ko0) : 0.f;
        float bias1 = (ko1 < KO) ? __ldg(b_off + ko1) : 0.f;
        #pragma unroll
        for (int ng = 0; ng < 2; ng++) {
            int nb = wn * 16 + ng * 8 + 2 * (lane & 3);
            if (ko0 < KO) {
                float* p = g_off + (((size_t)(b * KO + ko0) * H_ + ho) * W_ + nb);
                *(float2*)p = make_float2(c[ng][0] + bias0, c[ng][1] + bias0);
            }
            if (ko1 < KO) {
                float* p = g_off + (((size_t)(b * KO + ko1) * H_ + ho) * W_ + nb);
                *(float2*)p = make_float2(c[ng][2] + bias1, c[ng][3] + bias1);
            }
        }
    }
}

// ---------------- kernel 2: deformable conv (R11 structure + quad LDG.64 gather) ----------------
#define PITCH 144
__global__ void __launch_bounds__(256)
k_deform(float* __restrict__ out) {
    __shared__ __align__(16) char smA[128 * PITCH];   // 18432
    __shared__ __align__(16) char smB[64 * PITCH];    // 9216
    __shared__ __align__(16) float4 tapW4[576];       // 9216
    __shared__ __align__(16) int    tapI[576];        // 2304
    uint32_t sbA = smem_to_u32(smA);
    uint32_t sbB = smem_to_u32(smB);

    int b   = blockIdx.x >> 6;
    int ho  = blockIdx.x & 63;
    int tid = threadIdx.x;
    int wid = tid >> 5;
    int lane = tid & 31;

    // ---- precompute bilinear taps: quad form, row+col clamp folded into 4 weights ----
    const float* goff = g_off + (size_t)(b * KO) * (H_ * W_) + ho * W_;
    for (int it = tid; it < 576; it += 256) {
        int k  = it >> 6;
        int wo = it & 63;
        float dy = goff[(2 * k)     * (H_ * W_) + wo];
        float dx = goff[(2 * k + 1) * (H_ * W_) + wo];
        float py = (float)(ho - 1 + (k / 3)) + dy;
        float px = (float)(wo - 1 + (k % 3)) + dx;
        float y0f = floorf(py), x0f = floorf(px);
        float wy = py - y0f,    wx = px - x0f;
        int y0 = (int)y0f, x0 = (int)x0f;
        int y1 = y0 + 1,   x1 = x0 + 1;
        float vy0 = (y0 >= 0 && y0 < H_) ? 1.f : 0.f;
        float vy1 = (y1 >= 0 && y1 < H_) ? 1.f : 0.f;
        float vx0 = (x0 >= 0 && x0 < W_) ? 1.f : 0.f;
        float vx1 = (x1 >= 0 && x1 < W_) ? 1.f : 0.f;
        int cy0 = min(max(y0, 0), H_ - 1), cy1 = min(max(y1, 0), H_ - 1);
        int cx0 = min(max(x0, 0), W_ - 1), cx1 = min(max(x1, 0), W_ - 1);
        // validity-folded tap weights
        float w00 = (1.f - wy) * (1.f - wx) * vy0 * vx0;
        float w01 = (1.f - wy) * wx         * vy0 * vx1;
        float w10 = wy * (1.f - wx)         * vy1 * vx0;
        float w11 = wy * wx                 * vy1 * vx1;
        // quad base (always in-range for the packed tensor)
        int br = min(max(y0, 0), H_ - 2);
        int bc = min(max(x0, 0), W_ - 2);
        int ry0 = cy0 - br, ry1 = cy1 - br;   // 0/1
        int rx0 = cx0 - bc, rx1 = cx1 - bc;   // 0/1
        float wq00 = 0.f, wq01 = 0.f, wq10 = 0.f, wq11 = 0.f;
        // (ry0,rx0) += w00
        if (ry0 == 0) { if (rx0 == 0) wq00 += w00; else wq01 += w00; }
        else          { if (rx0 == 0) wq10 += w00; else wq11 += w00; }
        // (ry0,rx1) += w01
        if (ry0 == 0) { if (rx1 == 0) wq00 += w01; else wq01 += w01; }
        else          { if (rx1 == 0) wq10 += w01; else wq11 += w01; }
        // (ry1,rx0) += w10
        if (ry1 == 0) { if (rx0 == 0) wq00 += w10; else wq01 += w10; }
        else          { if (rx0 == 0) wq10 += w10; else wq11 += w10; }
        // (ry1,rx1) += w11
        if (ry1 == 0) { if (rx1 == 0) wq00 += w11; else wq01 += w11; }
        else          { if (rx1 == 0) wq10 += w11; else wq11 += w11; }
        tapW4[it] = make_float4(wq00, wq01, wq10, wq11);
        tapI[it]  = br * W_ + bc;
    }
    __syncthreads();   // taps visible before first gather

    float c[8][4];
    #pragma unroll
    for (int i = 0; i < 8; i++)
        #pragma unroll
        for (int j = 0; j < 4; j++) c[i][j] = 0.f;

    const uint2* xqb = g_xq + (size_t)b * (C_ * H_ * W_);
    const int n   = tid & 63;       // pixel this thread gathers
    const int t4  = tid >> 6;       // 16-channel block

    const int g8  = lane >> 3;
    const int lr  = lane & 7;
    const int m0  = wid * 16;
    const uint32_t a_row  = (uint32_t)(m0 + lr + (g8 & 1) * 8);
    const uint32_t a_koff = (uint32_t)((g8 >> 1) * 8);
    const uint32_t b_row  = (uint32_t)(lr + (g8 >> 1) * 8);
    const uint32_t b_koff = (uint32_t)((g8 & 1) * 8);

    const int a_m   = tid >> 1;          // A staging row
    const int a_c16 = (tid & 1) * 4;     // 64B half per thread

    for (int chunk = 0; chunk < NCHUNK; chunk++) {
        const int k9 = chunk >> 1;
        const int c0 = (chunk & 1) * 64;

        __syncthreads();   // prior MMA reads done before restage

        // ---- stage A (fp16 weights): 128 rows x 128B ----
        {
            const char* src = (const char*)g_wh + (size_t)a_m * (CK * 2)
                              + chunk * (KC * 2) + a_c16 * 16;
            char* dst = smA + a_m * PITCH + a_c16 * 16;
            uint4 u0 = *(const uint4*)(src);
            uint4 u1 = *(const uint4*)(src + 16);
            uint4 u2 = *(const uint4*)(src + 32);
            uint4 u3 = *(const uint4*)(src + 48);
            *(uint4*)(dst)      = u0;
            *(uint4*)(dst + 16) = u1;
            *(uint4*)(dst + 32) = u2;
            *(uint4*)(dst + 48) = u3;
        }

        // ---- gather B: 16 channels, ONE quad LDG.64 per value ----
        {
            int tb = k9 * 64 + n;
            int   ti = tapI[tb];
            float4 tw = tapW4[tb];
            const uint2* xc = xqb + (size_t)(c0 + t4 * 16) * (H_ * W_) + ti;
            float v[16];
            #pragma unroll
            for (int jj = 0; jj < 16; jj++) {
                uint2 q = __ldg(xc + (size_t)jj * (H_ * W_));
                float2 fa = __half22float2(*(__half2*)&q.x);
                float2 fb = __half22float2(*(__half2*)&q.y);
                float s = tw.x * fa.x;
                s = fmaf(tw.y, fa.y, s);
                s = fmaf(tw.z, fb.x, s);
                s = fmaf(tw.w, fb.y, s);
                v[jj] = s;
            }
            uint32_t* bw = (uint32_t*)(smB + n * PITCH + t4 * 32);
            #pragma unroll
            for (int q = 0; q < 8; q++) {
                __half2 h2 = __floats2half2_rn(v[2 * q], v[2 * q + 1]);
                bw[q] = *(uint32_t*)&h2;
            }
        }
        __syncthreads();   // A and B ready

        // ---- MMA: 4 k16-steps x 8 n8-tiles ----
        #pragma unroll
        for (int ks = 0; ks < 4; ks++) {
            uint32_t a0, a1, a2, a3;
            LDSM4(a0, a1, a2, a3, sbA + a_row * PITCH + (ks * 16 + a_koff) * 2);
            #pragma unroll
            for (int ng = 0; ng < 4; ng++) {
                uint32_t b0, b1, b2, b3;
                LDSM4(b0, b1, b2, b3, sbB + (ng * 16 + b_row) * PITCH + (ks * 16 + b_koff) * 2);
                MMA16816(c[ng * 2],     a0, a1, a2, a3, b0, b1);
                MMA16816(c[ng * 2 + 1], a0, a1, a2, a3, b2, b3);
            }
        }
    }

    // epilogue
    {
        int r0  = m0 + (lane >> 2);
        int col = 2 * (lane & 3);
        float* ob = out + (((size_t)(b * COUT)) * H_ + ho) * W_;
        #pragma unroll
        for (int t8 = 0; t8 < 8; t8++) {
            int nbase = t8 * 8 + col;
            float* p0 = ob + (size_t)r0 * (H_ * W_) + nbase;
            float* p1 = ob + (size_t)(r0 + 8) * (H_ * W_) + nbase;
            *(float2*)p0 = make_float2(c[t8][0], c[t8][1]);
            *(float2*)p1 = make_float2(c[t8][2], c[t8][3]);
        }
    }
}

// ---------------- launcher ----------------
extern "C" void kernel_launch(void* const* d_in, const int* in_sizes, int n_in,
                              void* d_out, int out_size) {
    const float* x     = (const float*)d_in[0];
    const float* w_off = (const float*)d_in[1];
    const float* b_off = (const float*)d_in[2];
    const float* w_def = (const float*)d_in[3];
    float* out = (float*)d_out;
    (void)in_sizes; (void)n_in; (void)out_size;

    k_prep_w<<<(COUT * CK + 255) / 256, 256>>>(w_def);
    k_prep_woff<<<(MOFF * CK + 255) / 256, 256>>>(w_off);
    k_prep_xq<<<B_ * C_, 256>>>(x);

    k_offmma<<<B_ * H_, 256>>>(x, b_off);
    k_deform<<<B_ * H_, 256>>>(out);
}

// round 16
// speedup vs baseline: 1.0266x; 1.0266x over previous
#include <cuda_runtime.h>
#include <cuda_fp16.h>
#include <cstdint>

// Problem constants
#define B_   8
#define C_   128
#define H_   64
#define W_   64
#define COUT 128
#define KO   18
#define CK   1152          // C_*9, K reordered as k9*128 + c
#define KC   64            // K per chunk
#define NCHUNK (CK / KC)   // 18
#define MOFF 32            // KO padded to 32 for MMA

__device__ __forceinline__ uint32_t smem_to_u32(const void* p) {
    uint32_t a;
    asm("{ .reg .u64 t; cvta.to.shared.u64 t, %1; cvt.u32.u64 %0, t; }" : "=r"(a) : "l"(p));
    return a;
}

// ldmatrix x4 (non-transposed)
#define LDSM4(r0, r1, r2, r3, addr) \
    asm volatile("ldmatrix.sync.aligned.m8n8.x4.shared.b16 {%0,%1,%2,%3}, [%4];" \
                 : "=r"(r0), "=r"(r1), "=r"(r2), "=r"(r3) : "r"(addr))

// fp16 mma with fp32 accumulate
#define MMA16816(c, a0, a1, a2, a3, b0, b1) \
    asm volatile("mma.sync.aligned.m16n8k16.row.col.f32.f16.f16.f32 " \
                 "{%0,%1,%2,%3},{%4,%5,%6,%7},{%8,%9},{%0,%1,%2,%3};" \
                 : "+f"((c)[0]), "+f"((c)[1]), "+f"((c)[2]), "+f"((c)[3]) \
                 : "r"(a0), "r"(a1), "r"(a2), "r"(a3), "r"(b0), "r"(b1))

// swizzled tile offset for k_offmma (128B rows, XOR on 16B granule)
__device__ __forceinline__ uint32_t sw_off(int row, int g16) {
    return (uint32_t)(row * 128 + ((g16 ^ (row & 7)) << 4));
}

// ---------------- device scratch ----------------
__device__ float g_off[B_ * KO * H_ * W_];
__device__ __align__(16) __half g_wh[COUT * CK];            // deform weights fp16, K = k9*128 + c
__device__ __align__(16) __half g_woh[MOFF * CK];           // offset-conv weights fp16, M padded
__device__ __align__(16) uint32_t g_xp[B_ * C_ * H_ * W_];  // half2(x[w], x[w+1]) pairs

// ---------------- kernel 0a: fp16 deform weights, k9-major reorder ----------------
__global__ void k_prep_w(const float* __restrict__ w_def) {
    int i = blockIdx.x * blockDim.x + threadIdx.x;
    if (i < COUT * CK) {
        int cout = i / CK;
        int rem  = i - cout * CK;
        int k9   = rem >> 7;
        int c    = rem & 127;
        g_wh[i] = __float2half(w_def[(cout * C_ + c) * 9 + k9]);
    }
}

// ---------------- kernel 0b: fp16 offset weights, k9-major, M padded to 32 ----------------
__global__ void k_prep_woff(const float* __restrict__ w_off) {
    int i = blockIdx.x * blockDim.x + threadIdx.x;
    if (i < MOFF * CK) {
        int m   = i / CK;
        int rem = i - m * CK;
        int k9  = rem >> 7;
        int c   = rem & 127;
        float v = (m < KO) ? w_off[(m * C_ + c) * 9 + k9] : 0.f;
        g_woh[i] = __float2half(v);
    }
}

// ---------------- kernel 0c: paired fp16 x ----------------
__global__ void k_prep_x(const float* __restrict__ x) {
    int t = blockIdx.x * blockDim.x + threadIdx.x;     // over B_*C_*H_*4
    if (t >= B_ * C_ * H_ * 4) return;
    int qid = t & 3;
    int rid = t >> 2;                                  // (b,c,h)
    const float* row = x + (size_t)rid * W_;
    int base = qid * 16;
    float4 v0 = *(const float4*)(row + base);
    float4 v1 = *(const float4*)(row + base + 4);
    float4 v2 = *(const float4*)(row + base + 8);
    float4 v3 = *(const float4*)(row + base + 12);
    float nxt = (qid < 3) ? row[base + 16] : row[W_ - 1];
    float f[17] = {v0.x,v0.y,v0.z,v0.w, v1.x,v1.y,v1.z,v1.w,
                   v2.x,v2.y,v2.z,v2.w, v3.x,v3.y,v3.z,v3.w, nxt};
    uint32_t o[16];
    #pragma unroll
    for (int j = 0; j < 16; j++) {
        __half2 h2 = __floats2half2_rn(f[j], f[j + 1]);
        o[j] = *(uint32_t*)&h2;
    }
    uint4* dst = (uint4*)(g_xp + (size_t)rid * W_ + base);
    dst[0] = make_uint4(o[0], o[1], o[2], o[3]);
    dst[1] = make_uint4(o[4], o[5], o[6], o[7]);
    dst[2] = make_uint4(o[8], o[9], o[10], o[11]);
    dst[3] = make_uint4(o[12], o[13], o[14], o[15]);
}

// ---------------- kernel 1: offsets conv via fp16 mma.sync (double-buffered, 1 sync/chunk) ----------------
__global__ void __launch_bounds__(256)
k_offmma(const float* __restrict__ x, const float* __restrict__ b_off) {
    __shared__ __align__(16) char smA[2][MOFF * 128];   // 2 x 4096
    __shared__ __align__(16) char smB[2][64 * 128];     // 2 x 8192

    int b   = blockIdx.x >> 6;
    int ho  = blockIdx.x & 63;
    int tid = threadIdx.x;
    int wid = tid >> 5;
    int lane = tid & 31;

    const int wm = wid & 1;
    const int wn = wid >> 1;

    float c[2][4];
    #pragma unroll
    for (int i = 0; i < 2; i++)
        #pragma unroll
        for (int j = 0; j < 4; j++) c[i][j] = 0.f;

    const int n  = tid & 63;
    const int t4 = tid >> 6;

    const int g8 = lane >> 3;
    const int lr = lane & 7;
    const int a_row = wm * 16 + lr + (g8 & 1) * 8;
    const int b_row = wn * 16 + lr + (g8 >> 1) * 8;
    const int ar7 = a_row & 7;
    const int br7 = b_row & 7;
    const int agl = g8 >> 1;
    const int bgl = g8 & 1;

    const int a_m  = tid >> 3;
    const int a_g  = tid & 7;

    for (int chunk = 0; chunk < NCHUNK; chunk++) {
        const int p  = chunk & 1;
        const int k9 = chunk >> 1;
        const int c0 = (chunk & 1) * 64;
        const int ky = k9 / 3;
        const int kx = k9 - ky * 3;

        // stage A into buffer p
        {
            const char* src = (const char*)g_woh + (size_t)a_m * (CK * 2)
                              + chunk * (KC * 2) + a_g * 16;
            *(uint4*)(smA[p] + sw_off(a_m, a_g)) = *(const uint4*)src;
        }
        // stage B into buffer p
        {
            int row = ho + ky - 1;
            int col = n + kx - 1;
            bool ok = ((unsigned)row < (unsigned)H_) && ((unsigned)col < (unsigned)W_);
            const float* base = x + (((size_t)(b * C_ + c0 + t4 * 16) * H_ + row) * W_ + col);
            uint32_t o[8];
            #pragma unroll
            for (int q = 0; q < 8; q++) {
                float va = ok ? __ldg(base + (size_t)(2 * q)     * (H_ * W_)) : 0.f;
                float vb = ok ? __ldg(base + (size_t)(2 * q + 1) * (H_ * W_)) : 0.f;
                __half2 h2 = __floats2half2_rn(va, vb);
                o[q] = *(uint32_t*)&h2;
            }
            *(uint4*)(smB[p] + sw_off(n, 2 * t4))     = make_uint4(o[0], o[1], o[2], o[3]);
            *(uint4*)(smB[p] + sw_off(n, 2 * t4 + 1)) = make_uint4(o[4], o[5], o[6], o[7]);
        }
        __syncthreads();   // buffer p ready; prior reads of p finished 2 chunks ago

        uint32_t sbA = smem_to_u32(smA[p]);
        uint32_t sbB = smem_to_u32(smB[p]);
        #pragma unroll
        for (int ks = 0; ks < 4; ks++) {
            uint32_t a0, a1, a2, a3;
            LDSM4(a0, a1, a2, a3, sbA + (uint32_t)(a_row * 128) + ((uint32_t)((2 * ks + agl) ^ ar7) << 4));
            uint32_t b0, b1, b2, b3;
            LDSM4(b0, b1, b2, b3, sbB + (uint32_t)(b_row * 128) + ((uint32_t)((2 * ks + bgl) ^ br7) << 4));
            MMA16816(c[0], a0, a1, a2, a3, b0, b1);
            MMA16816(c[1], a0, a1, a2, a3, b2, b3);
        }
        // no second sync: next iteration writes the OTHER buffer
    }

    {
        int ko0 = wm * 16 + (lane >> 2);
        int ko1 = ko0 + 8;
        float bias0 = (ko0 < KO) ? __ldg(b_off + ko0) : 0.f;
        float bias1 = (ko1 < KO) ? __ldg(b_off + ko1) : 0.f;
        #pragma unroll
        for (int ng = 0; ng < 2; ng++) {
            int nb = wn * 16 + ng * 8 + 2 * (lane & 3);
            if (ko0 < KO) {
                float* p_ = g_off + (((size_t)(b * KO + ko0) * H_ + ho) * W_ + nb);
                *(float2*)p_ = make_float2(c[ng][0] + bias0, c[ng][1] + bias0);
            }
            if (ko1 < KO) {
                float* p_ = g_off + (((size_t)(b * KO + ko1) * H_ + ho) * W_ + nb);
                *(float2*)p_ = make_float2(c[ng][2] + bias1, c[ng][3] + bias1);
            }
        }
    }
}

// ---------------- kernel 2: deformable conv (R11 gather + double buffers, 1 sync/chunk) ----------------
#define PITCH 144
#define DSA0  0
#define DSA1  (DSA0 + 128 * PITCH)        // 18432
#define DSB0  (DSA1 + 128 * PITCH)        // 36864
#define DSB1  (DSB0 + 64 * PITCH)         // 46080
#define DTAPW (DSB1 + 64 * PITCH)         // 55296: 576 float4
#define DTAPI (DTAPW + 576 * 16)          // 64512: 576 int2
#define DBYTES (DTAPI + 576 * 8)          // 69120

__global__ void __launch_bounds__(256)
k_deform(float* __restrict__ out) {
    extern __shared__ __align__(16) char smc[];
    float4* tapW4 = (float4*)(smc + DTAPW);
    int2*   tapI2 = (int2*)(smc + DTAPI);

    int b   = blockIdx.x >> 6;
    int ho  = blockIdx.x & 63;
    int tid = threadIdx.x;
    int wid = tid >> 5;
    int lane = tid & 31;

    // ---- precompute bilinear taps: paired-column form, clamp folded into weights ----
    const float* goff = g_off + (size_t)(b * KO) * (H_ * W_) + ho * W_;
    for (int it = tid; it < 576; it += 256) {
        int k  = it >> 6;
        int wo = it & 63;
        float dy = goff[(2 * k)     * (H_ * W_) + wo];
        float dx = goff[(2 * k + 1) * (H_ * W_) + wo];
        float py = (float)(ho - 1 + (k / 3)) + dy;
        float px = (float)(wo - 1 + (k % 3)) + dx;
        float y0f = floorf(py), x0f = floorf(px);
        float wy = py - y0f,    wx = px - x0f;
        int y0 = (int)y0f, x0 = (int)x0f;
        int y1 = y0 + 1,   x1 = x0 + 1;
        float vy0 = (y0 >= 0 && y0 < H_) ? 1.f : 0.f;
        float vy1 = (y1 >= 0 && y1 < H_) ? 1.f : 0.f;
        float vx0 = (x0 >= 0 && x0 < W_) ? 1.f : 0.f;
        float vx1 = (x1 >= 0 && x1 < W_) ? 1.f : 0.f;
        int cy0 = min(max(y0, 0), H_ - 1), cy1 = min(max(y1, 0), H_ - 1);
        int cx0 = min(max(x0, 0), W_ - 1), cx1 = min(max(x1, 0), W_ - 1);
        float w00 = (1.f - wy) * (1.f - wx) * vx0;
        float w01 = (1.f - wy) * wx         * vx1;
        float w10 = wy * (1.f - wx)         * vx0;
        float w11 = wy * wx                 * vx1;
        int bc = min(max(x0, 0), W_ - 2);
        float a0 = (cx0 == bc)     ? 1.f : 0.f;
        float a1 = (cx0 == bc + 1) ? 1.f : 0.f;
        float b0 = (cx1 == bc)     ? 1.f : 0.f;
        float b1 = (cx1 == bc + 1) ? 1.f : 0.f;
        tapW4[it] = make_float4((w00 * a0 + w01 * b0) * vy0,
                                (w00 * a1 + w01 * b1) * vy0,
                                (w10 * a0 + w11 * b0) * vy1,
                                (w10 * a1 + w11 * b1) * vy1);
        tapI2[it] = make_int2(cy0 * W_ + bc, cy1 * W_ + bc);
    }
    __syncthreads();   // taps visible before first gather

    float c[8][4];
    #pragma unroll
    for (int i = 0; i < 8; i++)
        #pragma unroll
        for (int j = 0; j < 4; j++) c[i][j] = 0.f;

    const uint32_t* xpb = g_xp + (size_t)b * C_ * H_ * W_;
    const int n   = tid & 63;
    const int t4  = tid >> 6;

    const int g8  = lane >> 3;
    const int lr  = lane & 7;
    const int m0  = wid * 16;
    const uint32_t a_row  = (uint32_t)(m0 + lr + (g8 & 1) * 8);
    const uint32_t a_koff = (uint32_t)((g8 >> 1) * 8);
    const uint32_t b_row  = (uint32_t)(lr + (g8 >> 1) * 8);
    const uint32_t b_koff = (uint32_t)((g8 & 1) * 8);

    const int a_m   = tid >> 1;
    const int a_c16 = (tid & 1) * 4;

    for (int chunk = 0; chunk < NCHUNK; chunk++) {
        const int p  = chunk & 1;
        const int k9 = chunk >> 1;
        const int c0 = (chunk & 1) * 64;
        char* SA = smc + (p ? DSA1 : DSA0);
        char* SB = smc + (p ? DSB1 : DSB0);

        // ---- stage A (fp16 weights) into buffer p ----
        {
            const char* src = (const char*)g_wh + (size_t)a_m * (CK * 2)
                              + chunk * (KC * 2) + a_c16 * 16;
            char* dst = SA + a_m * PITCH + a_c16 * 16;
            uint4 u0 = *(const uint4*)(src);
            uint4 u1 = *(const uint4*)(src + 16);
            uint4 u2 = *(const uint4*)(src + 32);
            uint4 u3 = *(const uint4*)(src + 48);
            *(uint4*)(dst)      = u0;
            *(uint4*)(dst + 16) = u1;
            *(uint4*)(dst + 32) = u2;
            *(uint4*)(dst + 48) = u3;
        }

        // ---- gather B into buffer p: 16 channels, 2 paired LDG.32 per value ----
        {
            int tb = k9 * 64 + n;
            int2   ti = tapI2[tb];
            float4 tw = tapW4[tb];
            const uint32_t* xc = xpb + (size_t)(c0 + t4 * 16) * (H_ * W_);
            uint32_t o[8];
            #pragma unroll
            for (int q = 0; q < 8; q++) {
                const uint32_t* xp0 = xc + (size_t)(2 * q) * (H_ * W_);
                const uint32_t* xp1 = xc + (size_t)(2 * q + 1) * (H_ * W_);
                uint32_t ua0 = __ldg(xp0 + ti.x);
                uint32_t ua1 = __ldg(xp0 + ti.y);
                uint32_t ub0 = __ldg(xp1 + ti.x);
                uint32_t ub1 = __ldg(xp1 + ti.y);
                float2 fa0 = __half22float2(*(__half2*)&ua0);
                float2 fa1 = __half22float2(*(__half2*)&ua1);
                float2 fb0 = __half22float2(*(__half2*)&ub0);
                float2 fb1 = __half22float2(*(__half2*)&ub1);
                float sa = tw.x * fa0.x;
                sa = fmaf(tw.y, fa0.y, sa);
                sa = fmaf(tw.z, fa1.x, sa);
                sa = fmaf(tw.w, fa1.y, sa);
                float sb_ = tw.x * fb0.x;
                sb_ = fmaf(tw.y, fb0.y, sb_);
                sb_ = fmaf(tw.z, fb1.x, sb_);
                sb_ = fmaf(tw.w, fb1.y, sb_);
                __half2 h2 = __floats2half2_rn(sa, sb_);
                o[q] = *(uint32_t*)&h2;
            }
            char* bw = SB + n * PITCH + t4 * 32;
            *(uint4*)(bw)      = make_uint4(o[0], o[1], o[2], o[3]);
            *(uint4*)(bw + 16) = make_uint4(o[4], o[5], o[6], o[7]);
        }
        __syncthreads();   // buffer p ready; reads of p finished 2 chunks ago

        // ---- MMA on buffer p: 4 k16-steps x 8 n8-tiles ----
        uint32_t sbA = smem_to_u32(SA);
        uint32_t sbB = smem_to_u32(SB);
        #pragma unroll
        for (int ks = 0; ks < 4; ks++) {
            uint32_t a0, a1, a2, a3;
            LDSM4(a0, a1, a2, a3, sbA + a_row * PITCH + (ks * 16 + a_koff) * 2);
            #pragma unroll
            for (int ng = 0; ng < 4; ng++) {
                uint32_t b0, b1, b2, b3;
                LDSM4(b0, b1, b2, b3, sbB + (ng * 16 + b_row) * PITCH + (ks * 16 + b_koff) * 2);
                MMA16816(c[ng * 2],     a0, a1, a2, a3, b0, b1);
                MMA16816(c[ng * 2 + 1], a0, a1, a2, a3, b2, b3);
            }
        }
        // no second sync: next iteration writes the OTHER buffer
    }

    // epilogue
    {
        int r0  = m0 + (lane >> 2);
        int col = 2 * (lane & 3);
        float* ob = out + (((size_t)(b * COUT)) * H_ + ho) * W_;
        #pragma unroll
        for (int t8 = 0; t8 < 8; t8++) {
            int nbase = t8 * 8 + col;
            float* p0 = ob + (size_t)r0 * (H_ * W_) + nbase;
            float* p1 = ob + (size_t)(r0 + 8) * (H_ * W_) + nbase;
            *(float2*)p0 = make_float2(c[t8][0], c[t8][1]);
            *(float2*)p1 = make_float2(c[t8][2], c[t8][3]);
        }
    }
}

// ---------------- launcher ----------------
extern "C" void kernel_launch(void* const* d_in, const int* in_sizes, int n_in,
                              void* d_out, int out_size) {
    const float* x     = (const float*)d_in[0];
    const float* w_off = (const float*)d_in[1];
    const float* b_off = (const float*)d_in[2];
    const float* w_def = (const float*)d_in[3];
    float* out = (float*)d_out;
    (void)in_sizes; (void)n_in; (void)out_size;

    k_prep_w<<<(COUT * CK + 255) / 256, 256>>>(w_def);
    k_prep_woff<<<(MOFF * CK + 255) / 256, 256>>>(w_off);
    k_prep_x<<<(B_ * C_ * H_ * 4 + 255) / 256, 256>>>(x);

    k_offmma<<<B_ * H_, 256>>>(x, b_off);

    cudaFuncSetAttribute(k_deform, cudaFuncAttributeMaxDynamicSharedMemorySize, DBYTES);
    k_deform<<<B_ * H_, 256, DBYTES>>>(out);
}

// round 17
// speedup vs baseline: 1.3618x; 1.3266x over previous
#include <cuda_runtime.h>
#include <cuda_fp16.h>
#include <cstdint>

// Problem constants
#define B_   8
#define C_   128
#define H_   64
#define W_   64
#define COUT 128
#define KO   18
#define CK   1152          // C_*9, K reordered as k9*128 + c
#define KC   64            // K per chunk
#define NCHUNK (CK / KC)   // 18
#define MOFF 32            // KO padded to 32 for MMA

__device__ __forceinline__ uint32_t smem_to_u32(const void* p) {
    uint32_t a;
    asm("{ .reg .u64 t; cvta.to.shared.u64 t, %1; cvt.u32.u64 %0, t; }" : "=r"(a) : "l"(p));
    return a;
}

// cp.async 16B (L2-only)
#define CP_ASYNC16(smem_addr, gptr) \
    asm volatile("cp.async.cg.shared.global [%0], [%1], 16;" \
                 :: "r"(smem_addr), "l"(gptr) : "memory")
#define CP_COMMIT()  asm volatile("cp.async.commit_group;" ::: "memory")
#define CP_WAIT0()   asm volatile("cp.async.wait_group 0;" ::: "memory")

// ldmatrix x4 (non-transposed)
#define LDSM4(r0, r1, r2, r3, addr) \
    asm volatile("ldmatrix.sync.aligned.m8n8.x4.shared.b16 {%0,%1,%2,%3}, [%4];" \
                 : "=r"(r0), "=r"(r1), "=r"(r2), "=r"(r3) : "r"(addr))

// fp16 mma with fp32 accumulate
#define MMA16816(c, a0, a1, a2, a3, b0, b1) \
    asm volatile("mma.sync.aligned.m16n8k16.row.col.f32.f16.f16.f32 " \
                 "{%0,%1,%2,%3},{%4,%5,%6,%7},{%8,%9},{%0,%1,%2,%3};" \
                 : "+f"((c)[0]), "+f"((c)[1]), "+f"((c)[2]), "+f"((c)[3]) \
                 : "r"(a0), "r"(a1), "r"(a2), "r"(a3), "r"(b0), "r"(b1))

// ---------------- device scratch ----------------
__device__ float g_off[B_ * KO * H_ * W_];
__device__ __align__(16) __half g_wh[COUT * CK];            // deform weights fp16, K = k9*128 + c
__device__ __align__(16) __half g_woh[MOFF * CK];           // offset-conv weights fp16, M padded
__device__ __align__(16) uint32_t g_xp[B_ * C_ * H_ * W_];  // half2(x[w], x[w+1]) pairs

// ---------------- kernel 0a: fp16 deform weights, k9-major reorder ----------------
__global__ void k_prep_w(const float* __restrict__ w_def) {
    int i = blockIdx.x * blockDim.x + threadIdx.x;
    if (i < COUT * CK) {
        int cout = i / CK;
        int rem  = i - cout * CK;
        int k9   = rem >> 7;
        int c    = rem & 127;
        g_wh[i] = __float2half(w_def[(cout * C_ + c) * 9 + k9]);
    }
}

// ---------------- kernel 0b: fp16 offset weights, k9-major, M padded to 32 ----------------
__global__ void k_prep_woff(const float* __restrict__ w_off) {
    int i = blockIdx.x * blockDim.x + threadIdx.x;
    if (i < MOFF * CK) {
        int m   = i / CK;
        int rem = i - m * CK;
        int k9  = rem >> 7;
        int c   = rem & 127;
        float v = (m < KO) ? w_off[(m * C_ + c) * 9 + k9] : 0.f;
        g_woh[i] = __float2half(v);
    }
}

// ---------------- kernel 0c: paired fp16 x ----------------
__global__ void k_prep_x(const float* __restrict__ x) {
    int t = blockIdx.x * blockDim.x + threadIdx.x;     // over B_*C_*H_*4
    if (t >= B_ * C_ * H_ * 4) return;
    int qid = t & 3;
    int rid = t >> 2;                                  // (b,c,h)
    const float* row = x + (size_t)rid * W_;
    int base = qid * 16;
    float4 v0 = *(const float4*)(row + base);
    float4 v1 = *(const float4*)(row + base + 4);
    float4 v2 = *(const float4*)(row + base + 8);
    float4 v3 = *(const float4*)(row + base + 12);
    float nxt = (qid < 3) ? row[base + 16] : row[W_ - 1];
    float f[17] = {v0.x,v0.y,v0.z,v0.w, v1.x,v1.y,v1.z,v1.w,
                   v2.x,v2.y,v2.z,v2.w, v3.x,v3.y,v3.z,v3.w, nxt};
    uint32_t o[16];
    #pragma unroll
    for (int j = 0; j < 16; j++) {
        __half2 h2 = __floats2half2_rn(f[j], f[j + 1]);
        o[j] = *(uint32_t*)&h2;
    }
    uint4* dst = (uint4*)(g_xp + (size_t)rid * W_ + base);
    dst[0] = make_uint4(o[0], o[1], o[2], o[3]);
    dst[1] = make_uint4(o[4], o[5], o[6], o[7]);
    dst[2] = make_uint4(o[8], o[9], o[10], o[11]);
    dst[3] = make_uint4(o[12], o[13], o[14], o[15]);
}

#define PITCH 144

// ---------------- kernel 1: offsets conv via fp16 mma.sync (R11 + cp.async A) ----------------
__global__ void __launch_bounds__(256)
k_offmma(const float* __restrict__ x, const float* __restrict__ b_off) {
    __shared__ __align__(16) char smc[MOFF * PITCH + 64 * PITCH];
    char* smA = smc;
    char* smB = smc + MOFF * PITCH;
    uint32_t sbA = smem_to_u32(smA);
    uint32_t sbB = smem_to_u32(smB);

    int b   = blockIdx.x >> 6;
    int ho  = blockIdx.x & 63;
    int tid = threadIdx.x;
    int wid = tid >> 5;
    int lane = tid & 31;

    const int wm = wid & 1;        // m16 stripe
    const int wn = wid >> 1;       // n16 stripe (0..3)

    float c[2][4];
    #pragma unroll
    for (int i = 0; i < 2; i++)
        #pragma unroll
        for (int j = 0; j < 4; j++) c[i][j] = 0.f;

    const int n  = tid & 63;       // pixel this thread stages
    const int t4 = tid >> 6;       // 16-channel block

    const int g8 = lane >> 3;
    const int lr = lane & 7;
    const uint32_t a_row  = (uint32_t)(wm * 16 + lr + (g8 & 1) * 8);
    const uint32_t a_koff = (uint32_t)((g8 >> 1) * 8);
    const uint32_t b_row  = (uint32_t)(wn * 16 + lr + (g8 >> 1) * 8);
    const uint32_t b_koff = (uint32_t)((g8 & 1) * 8);

    const int a_m   = tid >> 3;          // 0..31 rows
    const int a_c16 = tid & 7;           // 16B slot

    for (int chunk = 0; chunk < NCHUNK; chunk++) {
        const int k9 = chunk >> 1;
        const int c0 = (chunk & 1) * 64;
        const int ky = k9 / 3;
        const int kx = k9 - ky * 3;

        __syncthreads();   // prior MMA reads done

        // stage A via cp.async (latency hidden behind B gather)
        {
            const char* src = (const char*)g_woh + (size_t)a_m * (CK * 2)
                              + chunk * (KC * 2) + a_c16 * 16;
            CP_ASYNC16(sbA + (uint32_t)(a_m * PITCH + a_c16 * 16), src);
            CP_COMMIT();
        }

        // stage B: coalesced shifted row read, packed fp16 stores
        {
            int row = ho + ky - 1;
            int col = n + kx - 1;
            bool ok = ((unsigned)row < (unsigned)H_) && ((unsigned)col < (unsigned)W_);
            const float* base = x + (((size_t)(b * C_ + c0 + t4 * 16) * H_ + row) * W_ + col);
            uint32_t o[8];
            #pragma unroll
            for (int q = 0; q < 8; q++) {
                float va = ok ? __ldg(base + (size_t)(2 * q)     * (H_ * W_)) : 0.f;
                float vb = ok ? __ldg(base + (size_t)(2 * q + 1) * (H_ * W_)) : 0.f;
                __half2 h2 = __floats2half2_rn(va, vb);
                o[q] = *(uint32_t*)&h2;
            }
            char* bw = smB + n * PITCH + t4 * 32;
            *(uint4*)(bw)      = make_uint4(o[0], o[1], o[2], o[3]);
            *(uint4*)(bw + 16) = make_uint4(o[4], o[5], o[6], o[7]);
        }
        CP_WAIT0();
        __syncthreads();

        // MMA: m16 x n16 per warp, 4 k16-steps
        #pragma unroll
        for (int ks = 0; ks < 4; ks++) {
            uint32_t a0, a1, a2, a3;
            LDSM4(a0, a1, a2, a3, sbA + a_row * PITCH + (ks * 16 + a_koff) * 2);
            uint32_t b0, b1, b2, b3;
            LDSM4(b0, b1, b2, b3, sbB + b_row * PITCH + (ks * 16 + b_koff) * 2);
            MMA16816(c[0], a0, a1, a2, a3, b0, b1);
            MMA16816(c[1], a0, a1, a2, a3, b2, b3);
        }
    }

    // epilogue: add bias, store valid ko rows
    {
        int ko0 = wm * 16 + (lane >> 2);
        int ko1 = ko0 + 8;
        float bias0 = (ko0 < KO) ? __ldg(b_off + ko0) : 0.f;
        float bias1 = (ko1 < KO) ? __ldg(b_off + ko1) : 0.f;
        #pragma unroll
        for (int ng = 0; ng < 2; ng++) {
            int nb = wn * 16 + ng * 8 + 2 * (lane & 3);
            if (ko0 < KO) {
                float* p = g_off + (((size_t)(b * KO + ko0) * H_ + ho) * W_ + nb);
                *(float2*)p = make_float2(c[ng][0] + bias0, c[ng][1] + bias0);
            }
            if (ko1 < KO) {
                float* p = g_off + (((size_t)(b * KO + ko1) * H_ + ho) * W_ + nb);
                *(float2*)p = make_float2(c[ng][2] + bias1, c[ng][3] + bias1);
            }
        }
    }
}

// ---------------- kernel 2: deformable conv (R11 exact + cp.async A-staging) ----------------
#define SA    0
#define SB    (SA + 128 * PITCH)         // 18432: B, 64 rows
#define STAPW (SB + 64 * PITCH)          // 27648: 576 float4
#define STAPI (STAPW + 576 * 16)         // 36864: 576 int2
#define SBYTES (STAPI + 576 * 8)         // 41472

__global__ void __launch_bounds__(256)
k_deform(float* __restrict__ out) {
    extern __shared__ __align__(16) char smc[];
    uint32_t sb = smem_to_u32(smc);
    float4* tapW4 = (float4*)(smc + STAPW);
    int2*   tapI2 = (int2*)(smc + STAPI);

    int b   = blockIdx.x >> 6;
    int ho  = blockIdx.x & 63;
    int tid = threadIdx.x;
    int wid = tid >> 5;
    int lane = tid & 31;

    // ---- precompute bilinear taps: paired-column form with clamp folded into weights ----
    const float* goff = g_off + (size_t)(b * KO) * (H_ * W_) + ho * W_;
    for (int it = tid; it < 576; it += 256) {
        int k  = it >> 6;
        int wo = it & 63;
        float dy = goff[(2 * k)     * (H_ * W_) + wo];
        float dx = goff[(2 * k + 1) * (H_ * W_) + wo];
        float py = (float)(ho - 1 + (k / 3)) + dy;
        float px = (float)(wo - 1 + (k % 3)) + dx;
        float y0f = floorf(py), x0f = floorf(px);
        float wy = py - y0f,    wx = px - x0f;
        int y0 = (int)y0f, x0 = (int)x0f;
        int y1 = y0 + 1,   x1 = x0 + 1;
        float vy0 = (y0 >= 0 && y0 < H_) ? 1.f : 0.f;
        float vy1 = (y1 >= 0 && y1 < H_) ? 1.f : 0.f;
        float vx0 = (x0 >= 0 && x0 < W_) ? 1.f : 0.f;
        float vx1 = (x1 >= 0 && x1 < W_) ? 1.f : 0.f;
        int cy0 = min(max(y0, 0), H_ - 1), cy1 = min(max(y1, 0), H_ - 1);
        int cx0 = min(max(x0, 0), W_ - 1), cx1 = min(max(x1, 0), W_ - 1);
        float w00 = (1.f - wy) * (1.f - wx) * vx0;
        float w01 = (1.f - wy) * wx         * vx1;
        float w10 = wy * (1.f - wx)         * vx0;
        float w11 = wy * wx                 * vx1;
        int bc = min(max(x0, 0), W_ - 2);
        float a0 = (cx0 == bc)     ? 1.f : 0.f;
        float a1 = (cx0 == bc + 1) ? 1.f : 0.f;
        float b0 = (cx1 == bc)     ? 1.f : 0.f;
        float b1 = (cx1 == bc + 1) ? 1.f : 0.f;
        tapW4[it] = make_float4((w00 * a0 + w01 * b0) * vy0,
                                (w00 * a1 + w01 * b1) * vy0,
                                (w10 * a0 + w11 * b0) * vy1,
                                (w10 * a1 + w11 * b1) * vy1);
        tapI2[it] = make_int2(cy0 * W_ + bc, cy1 * W_ + bc);
    }
    __syncthreads();   // taps visible before first gather

    float c[8][4];
    #pragma unroll
    for (int i = 0; i < 8; i++)
        #pragma unroll
        for (int j = 0; j < 4; j++) c[i][j] = 0.f;

    const uint32_t* xpb = g_xp + (size_t)b * C_ * H_ * W_;
    const int n   = tid & 63;       // pixel this thread gathers
    const int t4  = tid >> 6;       // 16-channel block

    const int g8  = lane >> 3;
    const int lr  = lane & 7;
    const int m0  = wid * 16;
    const uint32_t a_row  = (uint32_t)(m0 + lr + (g8 & 1) * 8);
    const uint32_t a_koff = (uint32_t)((g8 >> 1) * 8);
    const uint32_t b_row  = (uint32_t)(lr + (g8 >> 1) * 8);
    const uint32_t b_koff = (uint32_t)((g8 & 1) * 8);

    const int a_m   = tid >> 1;          // A staging row
    const int a_c16 = (tid & 1) * 4;     // 64B half per thread

    for (int chunk = 0; chunk < NCHUNK; chunk++) {
        const int k9 = chunk >> 1;
        const int c0 = (chunk & 1) * 64;

        __syncthreads();   // prior MMA reads done before restage

        // ---- stage A via cp.async: 4 x 16B per thread, hidden behind gather ----
        {
            const char* src = (const char*)g_wh + (size_t)a_m * (CK * 2)
                              + chunk * (KC * 2) + a_c16 * 16;
            uint32_t dst = sb + SA + (uint32_t)(a_m * PITCH + a_c16 * 16);
            CP_ASYNC16(dst,      src);
            CP_ASYNC16(dst + 16, src + 16);
            CP_ASYNC16(dst + 32, src + 32);
            CP_ASYNC16(dst + 48, src + 48);
            CP_COMMIT();
        }

        // ---- gather B: 16 channels, 2 paired LDG per value (R11 exact) ----
        {
            int tb = k9 * 64 + n;
            int2   ti = tapI2[tb];
            float4 tw = tapW4[tb];
            const uint32_t* xc = xpb + (size_t)(c0 + t4 * 16) * (H_ * W_);
            uint32_t o[8];
            #pragma unroll
            for (int q = 0; q < 8; q++) {
                const uint32_t* xp0 = xc + (size_t)(2 * q) * (H_ * W_);
                const uint32_t* xp1 = xc + (size_t)(2 * q + 1) * (H_ * W_);
                uint32_t ua0 = __ldg(xp0 + ti.x);
                uint32_t ua1 = __ldg(xp0 + ti.y);
                uint32_t ub0 = __ldg(xp1 + ti.x);
                uint32_t ub1 = __ldg(xp1 + ti.y);
                float2 fa0 = __half22float2(*(__half2*)&ua0);
                float2 fa1 = __half22float2(*(__half2*)&ua1);
                float2 fb0 = __half22float2(*(__half2*)&ub0);
                float2 fb1 = __half22float2(*(__half2*)&ub1);
                float sa = tw.x * fa0.x;
                sa = fmaf(tw.y, fa0.y, sa);
                sa = fmaf(tw.z, fa1.x, sa);
                sa = fmaf(tw.w, fa1.y, sa);
                float sb_ = tw.x * fb0.x;
                sb_ = fmaf(tw.y, fb0.y, sb_);
                sb_ = fmaf(tw.z, fb1.x, sb_);
                sb_ = fmaf(tw.w, fb1.y, sb_);
                __half2 h2 = __floats2half2_rn(sa, sb_);
                o[q] = *(uint32_t*)&h2;
            }
            char* bw = smc + SB + n * PITCH + t4 * 32;
            *(uint4*)(bw)      = make_uint4(o[0], o[1], o[2], o[3]);
            *(uint4*)(bw + 16) = make_uint4(o[4], o[5], o[6], o[7]);
        }
        CP_WAIT0();        // A landed
        __syncthreads();   // A and B ready

        // ---- MMA: 4 k16-steps x 8 n8-tiles ----
        #pragma unroll
        for (int ks = 0; ks < 4; ks++) {
            uint32_t a0, a1, a2, a3;
            LDSM4(a0, a1, a2, a3, sb + SA + a_row * PITCH + (ks * 16 + a_koff) * 2);
            #pragma unroll
            for (int ng = 0; ng < 4; ng++) {
                uint32_t b0, b1, b2, b3;
                LDSM4(b0, b1, b2, b3, sb + SB + (ng * 16 + b_row) * PITCH + (ks * 16 + b_koff) * 2);
                MMA16816(c[ng * 2],     a0, a1, a2, a3, b0, b1);
                MMA16816(c[ng * 2 + 1], a0, a1, a2, a3, b2, b3);
            }
        }
    }

    // epilogue
    {
        int r0  = m0 + (lane >> 2);
        int col = 2 * (lane & 3);
        float* ob = out + (((size_t)(b * COUT)) * H_ + ho) * W_;
        #pragma unroll
        for (int t8 = 0; t8 < 8; t8++) {
            int nbase = t8 * 8 + col;
            float* p0 = ob + (size_t)r0 * (H_ * W_) + nbase;
            float* p1 = ob + (size_t)(r0 + 8) * (H_ * W_) + nbase;
            *(float2*)p0 = make_float2(c[t8][0], c[t8][1]);
            *(float2*)p1 = make_float2(c[t8][2], c[t8][3]);
        }
    }
}

// ---------------- launcher ----------------
extern "C" void kernel_launch(void* const* d_in, const int* in_sizes, int n_in,
                              void* d_out, int out_size) {
    const float* x     = (const float*)d_in[0];
    const float* w_off = (const float*)d_in[1];
    const float* b_off = (const float*)d_in[2];
    const float* w_def = (const float*)d_in[3];
    float* out = (float*)d_out;
    (void)in_sizes; (void)n_in; (void)out_size;

    k_prep_w<<<(COUT * CK + 255) / 256, 256>>>(w_def);
    k_prep_woff<<<(MOFF * CK + 255) / 256, 256>>>(w_off);
    k_prep_x<<<(B_ * C_ * H_ * 4 + 255) / 256, 256>>>(x);

    k_offmma<<<B_ * H_, 256>>>(x, b_off);

    cudaFuncSetAttribute(k_deform, cudaFuncAttributeMaxDynamicSharedMemorySize, SBYTES);
    k_deform<<<B_ * H_, 256, SBYTES>>>(out);
}